// round 15
// baseline (speedup 1.0000x reference)
#include <cuda_runtime.h>
#include <cuda_fp16.h>
#include <cstdint>

// Problem constants (fixed by the dataset)
#define NUM_NODES 20000
#define NUM_EDGES 65536
#define WIDTH     64
#define EDGE_FEAT 6
#define HIDDEN    128

// Scratch (allocation-free rule: __device__ globals)
__device__ float  g_h [(size_t)NUM_EDGES * HIDDEN];                // 33.5 MB (SORTED edge order)
__device__ __half g_gh[(size_t)NUM_NODES * HIDDEN * WIDTH];        // 328 MB  g[n][k][v] fp16
__device__ float  g_xb[(size_t)NUM_NODES * WIDTH];                 // 5.1 MB
__device__ __half g_wt[(size_t)HIDDEN * WIDTH * WIDTH];            // 2 MB  Wt[k][v][w] fp16
// edge sort-by-sender
__device__ int g_cnt [NUM_NODES];
__device__ int g_off [NUM_NODES + 1];
__device__ int g_inv [NUM_EDGES];     // original edge e -> sorted position
__device__ int g_ssnd[NUM_EDGES];     // sorted senders
__device__ int g_srcv[NUM_EDGES];     // sorted receivers

// Warp-level fp16 MMA (sm_80 PTX feature set — valid for plain sm_103 target)
#define MMA_FP16(c, a, b0, b1) \
    asm volatile("mma.sync.aligned.m16n8k16.row.col.f32.f16.f16.f32 " \
        "{%0,%1,%2,%3}, {%4,%5,%6,%7}, {%8,%9}, {%0,%1,%2,%3};" \
        : "+f"((c)[0]), "+f"((c)[1]), "+f"((c)[2]), "+f"((c)[3]) \
        : "r"((a)[0]), "r"((a)[1]), "r"((a)[2]), "r"((a)[3]), "r"(b0), "r"(b1))

// ---------------------------------------------------------------------------
// Zero kernels
// ---------------------------------------------------------------------------
__global__ void k_zero(float* __restrict__ out, int n) {
    int i = blockIdx.x * blockDim.x + threadIdx.x;
    if (i < n) out[i] = 0.f;
}
__global__ void k_zero_cnt() {
    int i = blockIdx.x * blockDim.x + threadIdx.x;
    if (i < NUM_NODES) g_cnt[i] = 0;
}

// ---------------------------------------------------------------------------
// Edge sort-by-sender: count -> scan (1 block) -> fill (inv/sorted arrays)
// ---------------------------------------------------------------------------
__global__ void k_count(const int* __restrict__ snd) {
    int i = blockIdx.x * blockDim.x + threadIdx.x;
    if (i < NUM_EDGES) atomicAdd(&g_cnt[snd[i]], 1);
}
__global__ __launch_bounds__(1024) void k_scan() {
    __shared__ int ps[1024];
    const int tid = threadIdx.x;
    const int CH  = (NUM_NODES + 1023) / 1024;   // 20
    const int base = tid * CH;
    int s = 0;
    #pragma unroll
    for (int j = 0; j < CH; j++) {
        int i = base + j;
        if (i < NUM_NODES) s += g_cnt[i];
    }
    ps[tid] = s;
    __syncthreads();
    for (int d = 1; d < 1024; d <<= 1) {         // Hillis-Steele inclusive scan
        int v = (tid >= d) ? ps[tid - d] : 0;
        __syncthreads();
        ps[tid] += v;
        __syncthreads();
    }
    int run = ps[tid] - s;                        // exclusive prefix of chunk
    #pragma unroll
    for (int j = 0; j < CH; j++) {
        int i = base + j;
        if (i < NUM_NODES) { g_off[i] = run; run += g_cnt[i]; g_cnt[i] = 0; }
    }
    if (tid == 1023) g_off[NUM_NODES] = run;
}
__global__ void k_fill(const int* __restrict__ snd, const int* __restrict__ rcv) {
    int i = blockIdx.x * blockDim.x + threadIdx.x;
    if (i >= NUM_EDGES) return;
    int s = snd[i];
    int pos = g_off[s] + atomicAdd(&g_cnt[s], 1);
    g_inv[i]     = pos;
    g_ssnd[pos]  = s;
    g_srcv[pos]  = rcv[i];
}

// ---------------------------------------------------------------------------
// h[pos][k] = relu( sum_f edge_attr[e][f]*W1[f][k] + b1[k] ), pos = g_inv[e]
// ---------------------------------------------------------------------------
__global__ void k_hidden(const float* __restrict__ ea,
                         const float* __restrict__ W1,
                         const float* __restrict__ b1) {
    int idx = blockIdx.x * blockDim.x + threadIdx.x;
    if (idx >= NUM_EDGES * HIDDEN) return;
    int e = idx >> 7;
    int j = idx & (HIDDEN - 1);
    const float* a = ea + (size_t)e * EDGE_FEAT;
    float s = __ldg(b1 + j);
    #pragma unroll
    for (int f = 0; f < EDGE_FEAT; f++)
        s = fmaf(__ldg(a + f), __ldg(W1 + f * HIDDEN + j), s);
    g_h[(size_t)g_inv[e] * HIDDEN + j] = fmaxf(s, 0.f);
}

// ---------------------------------------------------------------------------
// Wt[k][v][w] = W2[k][w*64+v] as fp16 (col-major B for mma.row.col)
// ---------------------------------------------------------------------------
__global__ void k_prep_w2(const float* __restrict__ W2) {
    int idx = blockIdx.x * blockDim.x + threadIdx.x;
    if (idx >= HIDDEN * WIDTH * WIDTH) return;
    int k = idx >> 12, rem = idx & 4095, v = rem >> 6, w = rem & 63;
    g_wt[idx] = __float2half_rn(W2[(size_t)k * 4096 + w * 64 + v]);
}

// ---------------------------------------------------------------------------
// xb[n][v] = sum_w x[n][w]*b2[w*64+v].  16 nodes/block, 4 outputs/thread.
// ---------------------------------------------------------------------------
__global__ __launch_bounds__(256) void k_xb(const float* __restrict__ x,
                                            const float* __restrict__ b2) {
    __shared__ float b2s[WIDTH * WIDTH];       // 16 KB, [w][v]
    __shared__ float xs[16][WIDTH + 1];        // 16 node rows, padded
    const int t = threadIdx.x;
    for (int i = t; i < WIDTH * WIDTH; i += 256)
        b2s[i] = b2[i];
    {
        const int n0 = blockIdx.x * 16;
        for (int i = t; i < 16 * WIDTH; i += 256) {
            int nl = i >> 6, w = i & 63;
            int n = n0 + nl;
            xs[nl][w] = (n < NUM_NODES) ? x[(size_t)n * WIDTH + w] : 0.f;
        }
    }
    __syncthreads();

    const int nl = t >> 4;
    const int v4 = t & 15;
    float4 acc = make_float4(0.f, 0.f, 0.f, 0.f);
    #pragma unroll 8
    for (int w = 0; w < WIDTH; w++) {
        const float xv = xs[nl][w];
        const float4 b = *(const float4*)&b2s[w * WIDTH + v4 * 4];
        acc.x = fmaf(xv, b.x, acc.x);
        acc.y = fmaf(xv, b.y, acc.y);
        acc.z = fmaf(xv, b.z, acc.z);
        acc.w = fmaf(xv, b.w, acc.w);
    }
    const int n = blockIdx.x * 16 + nl;
    if (n < NUM_NODES)
        *(float4*)(g_xb + (size_t)n * WIDTH + v4 * 4) = acc;
}

// ---------------------------------------------------------------------------
// HMMA g-GEMM: g[n][k][v] = sum_w x[n][w]*Wt[k][v][w], fp16 in / fp32 acc /
// fp16 out. Single MMA group. CTA = 128-node M-tile; 8 warps (4m x 2n),
// 32x32 C tile. A frags register-resident; B register-prefetched into
// double-buffered smem, ONE barrier/plane. occ 2.
// ---------------------------------------------------------------------------
#define KP 72
#define SMA 0                                  // 128 rows * 144B = 18432
#define SMB_BASE (128 * KP * 2)                // 18432
#define SMB(p) (SMB_BASE + (p) * 9216)         // 64 rows * 144B each
#define SM_TOT (SMB_BASE + 2 * 9216)           // 36864 bytes (x2 CTAs = 74KB)

__global__ __launch_bounds__(256, 2) void k_gmat_hmma(const float* __restrict__ x) {
    extern __shared__ char sm[];
    const int t    = threadIdx.x;
    const int lane = t & 31;
    const int warp = t >> 5;
    const int wm   = warp & 3;
    const int wn   = warp >> 2;
    const int n0   = blockIdx.x * 128;
    const int g    = lane >> 2;
    const int l4   = lane & 3;

    // ---- Stage A tile: x rows -> fp16, padded KP-stride rows ----
    {
        const int row  = t >> 1;
        const int half = t & 1;
        const int n    = n0 + row;
        float4 f4[8];
        if (n < NUM_NODES) {
            const float4* xr = (const float4*)(x + (size_t)n * WIDTH) + half * 8;
            #pragma unroll
            for (int j = 0; j < 8; j++) f4[j] = xr[j];
        } else {
            #pragma unroll
            for (int j = 0; j < 8; j++) f4[j] = make_float4(0.f, 0.f, 0.f, 0.f);
        }
        const float* f = (const float*)f4;
        #pragma unroll
        for (int c = 0; c < 4; c++) {
            uint32_t hw[4];
            #pragma unroll
            for (int j = 0; j < 4; j++) {
                __half2 h2 = __floats2half2_rn(f[c * 8 + j * 2], f[c * 8 + j * 2 + 1]);
                hw[j] = *(uint32_t*)&h2;
            }
            const uint32_t off = (uint32_t)row * (KP * 2) + half * 64 + c * 16;
            *(uint4*)(sm + SMA + off) = make_uint4(hw[0], hw[1], hw[2], hw[3]);
        }
    }

    const uint4* wt4 = (const uint4*)g_wt;     // 512 uint4 per plane
    const int i0 = t, i1 = t + 256;
    const uint32_t so0 = (uint32_t)(i0 >> 3) * (KP * 2) + (i0 & 7) * 16;
    const uint32_t so1 = (uint32_t)(i1 >> 3) * (KP * 2) + (i1 & 7) * 16;

    // ---- Stage B plane 0 into buffer 0 ----
    {
        uint4 a0 = wt4[i0], a1 = wt4[i1];
        *(uint4*)(sm + SMB(0) + so0) = a0;
        *(uint4*)(sm + SMB(0) + so1) = a1;
    }
    __syncthreads();   // A tile + B plane 0 visible

    // ---- Load A fragments once (register-resident, 32 regs) ----
    uint32_t Ah[2][4][4];
    #pragma unroll
    for (int mt = 0; mt < 2; mt++) {
        #pragma unroll
        for (int kt = 0; kt < 4; kt++) {
            const int r0 = wm * 32 + mt * 16 + g;
            const int cb = kt * 16 + l4 * 2;
            Ah[mt][kt][0] = *(const uint32_t*)(sm + SMA + ((size_t)r0 * KP + cb) * 2);
            Ah[mt][kt][1] = *(const uint32_t*)(sm + SMA + ((size_t)(r0 + 8) * KP + cb) * 2);
            Ah[mt][kt][2] = *(const uint32_t*)(sm + SMA + ((size_t)r0 * KP + cb + 8) * 2);
            Ah[mt][kt][3] = *(const uint32_t*)(sm + SMA + ((size_t)(r0 + 8) * KP + cb + 8) * 2);
        }
    }

    // ---- Plane loop: compute from buf p; prefetch k+1 via regs -> buf p^1;
    //      ONE __syncthreads per plane. 32 MMAs/warp/plane. ----
    for (int k = 0; k < HIDDEN; k++) {
        const int p = k & 1;
        uint4 ph0, ph1;
        const bool pre = (k + 1 < HIDDEN);
        if (pre) {                        // issue LDGs early; MMAs hide latency
            const size_t base = (size_t)(k + 1) * 512;
            ph0 = wt4[base + i0];  ph1 = wt4[base + i1];
        }

        float C[2][4][4];
        #pragma unroll
        for (int mt = 0; mt < 2; mt++)
            #pragma unroll
            for (int nt = 0; nt < 4; nt++)
                #pragma unroll
                for (int i = 0; i < 4; i++) C[mt][nt][i] = 0.f;

        #pragma unroll
        for (int kt = 0; kt < 4; kt++) {
            #pragma unroll
            for (int nt = 0; nt < 4; nt++) {
                const uint32_t boff =
                    ((uint32_t)(wn * 32 + nt * 8 + g) * KP + kt * 16 + l4 * 2) * 2;
                const uint32_t b0 = *(const uint32_t*)(sm + SMB(p) + boff);
                const uint32_t b1 = *(const uint32_t*)(sm + SMB(p) + boff + 16);
                #pragma unroll
                for (int mt = 0; mt < 2; mt++)
                    MMA_FP16(C[mt][nt], Ah[mt][kt], b0, b1);
            }
        }

        if (pre) {                        // STS into the idle buffer (no race)
            *(uint4*)(sm + SMB(p ^ 1) + so0) = ph0;
            *(uint4*)(sm + SMB(p ^ 1) + so1) = ph1;
        }

        // Store this k-plane as fp16
        #pragma unroll
        for (int mt = 0; mt < 2; mt++) {
            const int n1 = n0 + wm * 32 + mt * 16 + g;
            const int n2 = n1 + 8;
            #pragma unroll
            for (int nt = 0; nt < 4; nt++) {
                const int col = wn * 32 + nt * 8 + l4 * 2;
                if (n1 < NUM_NODES)
                    *(__half2*)(g_gh + ((size_t)n1 * HIDDEN + k) * WIDTH + col) =
                        __floats2half2_rn(C[mt][nt][0], C[mt][nt][1]);
                if (n2 < NUM_NODES)
                    *(__half2*)(g_gh + ((size_t)n2 * HIDDEN + k) * WIDTH + col) =
                        __floats2half2_rn(C[mt][nt][2], C[mt][nt][3]);
            }
        }

        if (pre) __syncthreads();         // buf p^1 ready; buf p free next plane
    }
}

// ---------------------------------------------------------------------------
// SPLIT-K k_msg: TWO warps per sorted edge i, each covering 64 k-planes
// (halves the FMA dependency chain + exposed gather latency; doubles warp
// parallelism). Even warp seeds acc with xb, odd with 0; both atomicAdd.
// ---------------------------------------------------------------------------
__global__ __launch_bounds__(256) void k_msg(float* __restrict__ out) {
    __shared__ float hs[8][64];
    const int wi   = threadIdx.x >> 5;
    const int lane = threadIdx.x & 31;
    const int i    = blockIdx.x * 4 + (wi >> 1);
    const int half = wi & 1;
    if (i >= NUM_EDGES) return;

    hs[wi][lane]      = g_h[(size_t)i * HIDDEN + half * 64 + lane];
    hs[wi][lane + 32] = g_h[(size_t)i * HIDDEN + half * 64 + lane + 32];
    __syncwarp();

    const int s = g_ssnd[i];
    const int r = g_srcv[i];

    const __half2* gp =
        (const __half2*)(g_gh + ((size_t)s * HIDDEN + half * 64) * WIDTH) + lane;
    float2 acc = (half == 0)
        ? ((const float2*)(g_xb + (size_t)s * WIDTH))[lane]
        : make_float2(0.f, 0.f);

    #pragma unroll 8
    for (int k = 0; k < 64; k++) {
        float hk = hs[wi][k];
        if (hk != 0.f) {
            float2 gv = __half22float2(gp[k * 32]);   // 128B coalesced row
            acc.x = fmaf(hk, gv.x, acc.x);
            acc.y = fmaf(hk, gv.y, acc.y);
        }
    }

    atomicAdd(out + (size_t)r * WIDTH + 2 * lane,     acc.x);
    atomicAdd(out + (size_t)r * WIDTH + 2 * lane + 1, acc.y);
}

// ---------------------------------------------------------------------------
// Launch: fork-join two streams (same deps as R14). Submission order makes
// k_gmat_hmma the 4th kernel submission -> ncu profiles it (empirically the
// 4th submission is the one captured).
// ---------------------------------------------------------------------------
extern "C" void kernel_launch(void* const* d_in, const int* in_sizes, int n_in,
                              void* d_out, int out_size) {
    const float* x   = (const float*)d_in[0];
    const float* ea  = (const float*)d_in[1];
    const float* W1  = (const float*)d_in[2];
    const float* b1  = (const float*)d_in[3];
    const float* W2  = (const float*)d_in[4];
    const float* b2  = (const float*)d_in[5];
    const int*   snd = (const int*)d_in[6];
    const int*   rcv = (const int*)d_in[7];
    float* out = (float*)d_out;

    static cudaStream_t s2 = nullptr;
    static cudaEvent_t  evF = nullptr, evJ = nullptr;
    if (!s2) {
        cudaStreamCreateWithFlags(&s2, cudaStreamNonBlocking);
        cudaEventCreateWithFlags(&evF, cudaEventDisableTiming);
        cudaEventCreateWithFlags(&evJ, cudaEventDisableTiming);
        cudaFuncSetAttribute(k_gmat_hmma,
                             cudaFuncAttributeMaxDynamicSharedMemorySize, SM_TOT);
    }

    // ---- fork ----
    cudaEventRecord(evF, 0);
    cudaStreamWaitEvent(s2, evF, 0);

    // launches 1-2 (default stream)
    k_zero_cnt<<<(NUM_NODES + 255) / 256, 256>>>();
    k_count<<<(NUM_EDGES + 255) / 256, 256>>>(snd);

    // launches 3-4 (side stream; gmat is the 4th kernel submission -> profiled)
    k_prep_w2<<<(HIDDEN * WIDTH * WIDTH + 255) / 256, 256, 0, s2>>>(W2);
    k_gmat_hmma<<<(NUM_NODES + 127) / 128, 256, SM_TOT, s2>>>(x);
    cudaEventRecord(evJ, s2);

    // rest of default stream (independent of g)
    k_scan<<<1, 1024>>>();
    k_fill<<<(NUM_EDGES + 255) / 256, 256>>>(snd, rcv);
    k_hidden<<<(NUM_EDGES * HIDDEN + 255) / 256, 256>>>(ea, W1, b1);
    k_xb<<<(NUM_NODES + 15) / 16, 256>>>(x, b2);
    k_zero<<<(NUM_NODES * WIDTH + 255) / 256, 256>>>(out, NUM_NODES * WIDTH);

    // ---- join, then the gather/scatter ----
    cudaStreamWaitEvent((cudaStream_t)0, evJ, 0);
    k_msg<<<NUM_EDGES / 4, 256>>>(out);
}

// round 16
// speedup vs baseline: 1.1524x; 1.1524x over previous
#include <cuda_runtime.h>
#include <cuda_fp16.h>
#include <cstdint>

// Problem constants (fixed by the dataset)
#define NUM_NODES 20000
#define NUM_EDGES 65536
#define WIDTH     64
#define EDGE_FEAT 6
#define HIDDEN    128

// Scratch (allocation-free rule: __device__ globals)
__device__ float  g_h [(size_t)NUM_EDGES * HIDDEN];                // 33.5 MB (SORTED edge order)
__device__ __half g_gh[(size_t)NUM_NODES * HIDDEN * WIDTH];        // 328 MB  g[n][k][v] fp16
__device__ float  g_xb[(size_t)NUM_NODES * WIDTH];                 // 5.1 MB
__device__ __half g_wt[(size_t)HIDDEN * WIDTH * WIDTH];            // 2 MB  Wt[k][v][w] fp16
// edge sort-by-sender
__device__ int g_cnt [NUM_NODES];
__device__ int g_off [NUM_NODES + 1];
__device__ int g_inv [NUM_EDGES];     // original edge e -> sorted position
__device__ int g_ssnd[NUM_EDGES];     // sorted senders
__device__ int g_srcv[NUM_EDGES];     // sorted receivers

// Warp-level fp16 MMA (sm_80 PTX feature set — valid for plain sm_103 target)
#define MMA_FP16(c, a, b0, b1) \
    asm volatile("mma.sync.aligned.m16n8k16.row.col.f32.f16.f16.f32 " \
        "{%0,%1,%2,%3}, {%4,%5,%6,%7}, {%8,%9}, {%0,%1,%2,%3};" \
        : "+f"((c)[0]), "+f"((c)[1]), "+f"((c)[2]), "+f"((c)[3]) \
        : "r"((a)[0]), "r"((a)[1]), "r"((a)[2]), "r"((a)[3]), "r"(b0), "r"(b1))

// ---------------------------------------------------------------------------
// Zero kernels
// ---------------------------------------------------------------------------
__global__ void k_zero(float* __restrict__ out, int n) {
    int i = blockIdx.x * blockDim.x + threadIdx.x;
    if (i < n) out[i] = 0.f;
}
__global__ void k_zero_cnt() {
    int i = blockIdx.x * blockDim.x + threadIdx.x;
    if (i < NUM_NODES) g_cnt[i] = 0;
}

// ---------------------------------------------------------------------------
// Edge sort-by-sender: count -> scan (1 block) -> fill (inv/sorted arrays)
// ---------------------------------------------------------------------------
__global__ void k_count(const int* __restrict__ snd) {
    int i = blockIdx.x * blockDim.x + threadIdx.x;
    if (i < NUM_EDGES) atomicAdd(&g_cnt[snd[i]], 1);
}
__global__ __launch_bounds__(1024) void k_scan() {
    __shared__ int ps[1024];
    const int tid = threadIdx.x;
    const int CH  = (NUM_NODES + 1023) / 1024;   // 20
    const int base = tid * CH;
    int s = 0;
    #pragma unroll
    for (int j = 0; j < CH; j++) {
        int i = base + j;
        if (i < NUM_NODES) s += g_cnt[i];
    }
    ps[tid] = s;
    __syncthreads();
    for (int d = 1; d < 1024; d <<= 1) {         // Hillis-Steele inclusive scan
        int v = (tid >= d) ? ps[tid - d] : 0;
        __syncthreads();
        ps[tid] += v;
        __syncthreads();
    }
    int run = ps[tid] - s;                        // exclusive prefix of chunk
    #pragma unroll
    for (int j = 0; j < CH; j++) {
        int i = base + j;
        if (i < NUM_NODES) { g_off[i] = run; run += g_cnt[i]; g_cnt[i] = 0; }
    }
    if (tid == 1023) g_off[NUM_NODES] = run;
}
__global__ void k_fill(const int* __restrict__ snd, const int* __restrict__ rcv) {
    int i = blockIdx.x * blockDim.x + threadIdx.x;
    if (i >= NUM_EDGES) return;
    int s = snd[i];
    int pos = g_off[s] + atomicAdd(&g_cnt[s], 1);
    g_inv[i]     = pos;
    g_ssnd[pos]  = s;
    g_srcv[pos]  = rcv[i];
}

// ---------------------------------------------------------------------------
// h[pos][k] = relu( sum_f edge_attr[e][f]*W1[f][k] + b1[k] ), pos = g_inv[e]
// ---------------------------------------------------------------------------
__global__ void k_hidden(const float* __restrict__ ea,
                         const float* __restrict__ W1,
                         const float* __restrict__ b1) {
    int idx = blockIdx.x * blockDim.x + threadIdx.x;
    if (idx >= NUM_EDGES * HIDDEN) return;
    int e = idx >> 7;
    int j = idx & (HIDDEN - 1);
    const float* a = ea + (size_t)e * EDGE_FEAT;
    float s = __ldg(b1 + j);
    #pragma unroll
    for (int f = 0; f < EDGE_FEAT; f++)
        s = fmaf(__ldg(a + f), __ldg(W1 + f * HIDDEN + j), s);
    g_h[(size_t)g_inv[e] * HIDDEN + j] = fmaxf(s, 0.f);
}

// ---------------------------------------------------------------------------
// Wt[k][v][w] = W2[k][w*64+v] as fp16 (col-major B for mma.row.col)
// ---------------------------------------------------------------------------
__global__ void k_prep_w2(const float* __restrict__ W2) {
    int idx = blockIdx.x * blockDim.x + threadIdx.x;
    if (idx >= HIDDEN * WIDTH * WIDTH) return;
    int k = idx >> 12, rem = idx & 4095, v = rem >> 6, w = rem & 63;
    g_wt[idx] = __float2half_rn(W2[(size_t)k * 4096 + w * 64 + v]);
}

// ---------------------------------------------------------------------------
// xb[n][v] = sum_w x[n][w]*b2[w*64+v].  16 nodes/block, 4 outputs/thread.
// ---------------------------------------------------------------------------
__global__ __launch_bounds__(256) void k_xb(const float* __restrict__ x,
                                            const float* __restrict__ b2) {
    __shared__ float b2s[WIDTH * WIDTH];       // 16 KB, [w][v]
    __shared__ float xs[16][WIDTH + 1];        // 16 node rows, padded
    const int t = threadIdx.x;
    for (int i = t; i < WIDTH * WIDTH; i += 256)
        b2s[i] = b2[i];
    {
        const int n0 = blockIdx.x * 16;
        for (int i = t; i < 16 * WIDTH; i += 256) {
            int nl = i >> 6, w = i & 63;
            int n = n0 + nl;
            xs[nl][w] = (n < NUM_NODES) ? x[(size_t)n * WIDTH + w] : 0.f;
        }
    }
    __syncthreads();

    const int nl = t >> 4;
    const int v4 = t & 15;
    float4 acc = make_float4(0.f, 0.f, 0.f, 0.f);
    #pragma unroll 8
    for (int w = 0; w < WIDTH; w++) {
        const float xv = xs[nl][w];
        const float4 b = *(const float4*)&b2s[w * WIDTH + v4 * 4];
        acc.x = fmaf(xv, b.x, acc.x);
        acc.y = fmaf(xv, b.y, acc.y);
        acc.z = fmaf(xv, b.z, acc.z);
        acc.w = fmaf(xv, b.w, acc.w);
    }
    const int n = blockIdx.x * 16 + nl;
    if (n < NUM_NODES)
        *(float4*)(g_xb + (size_t)n * WIDTH + v4 * 4) = acc;
}

// ---------------------------------------------------------------------------
// HMMA g-GEMM: g[n][k][v] = sum_w x[n][w]*Wt[k][v][w], fp16 in/fp32 acc/fp16 out.
// GRID (157, 2): CTA (bx,by) = 128-node M-tile x 64-plane slice. R15 profile
// showed occ 12.8% (ONE CTA/SM: grid 157 < 148x2 slots) -> tensor 15%,
// issue 11%. Doubling the grid via plane-split fills occupancy 2 (314 >= 296
// slots): 4 warps/SMSP, 2x latency hiding, half the serial work per CTA.
// A frags register-resident; B reg-prefetched, double-buffered smem,
// ONE barrier/plane.
// ---------------------------------------------------------------------------
#define KP 72
#define SMA 0                                  // 128 rows * 144B = 18432
#define SMB_BASE (128 * KP * 2)                // 18432
#define SMB(p) (SMB_BASE + (p) * 9216)         // 64 rows * 144B each
#define SM_TOT (SMB_BASE + 2 * 9216)           // 36864 bytes (x2 CTAs = 74KB)
#define KSPLIT 2
#define KCHUNK (HIDDEN / KSPLIT)               // 64 planes per CTA

__global__ __launch_bounds__(256, 2) void k_gmat_hmma(const float* __restrict__ x) {
    extern __shared__ char sm[];
    const int t     = threadIdx.x;
    const int lane  = t & 31;
    const int warp  = t >> 5;
    const int wm    = warp & 3;
    const int wn    = warp >> 2;
    const int n0    = blockIdx.x * 128;
    const int kbase = blockIdx.y * KCHUNK;
    const int g     = lane >> 2;
    const int l4    = lane & 3;

    // ---- Stage A tile: x rows -> fp16, padded KP-stride rows ----
    {
        const int row  = t >> 1;
        const int half = t & 1;
        const int n    = n0 + row;
        float4 f4[8];
        if (n < NUM_NODES) {
            const float4* xr = (const float4*)(x + (size_t)n * WIDTH) + half * 8;
            #pragma unroll
            for (int j = 0; j < 8; j++) f4[j] = xr[j];
        } else {
            #pragma unroll
            for (int j = 0; j < 8; j++) f4[j] = make_float4(0.f, 0.f, 0.f, 0.f);
        }
        const float* f = (const float*)f4;
        #pragma unroll
        for (int c = 0; c < 4; c++) {
            uint32_t hw[4];
            #pragma unroll
            for (int j = 0; j < 4; j++) {
                __half2 h2 = __floats2half2_rn(f[c * 8 + j * 2], f[c * 8 + j * 2 + 1]);
                hw[j] = *(uint32_t*)&h2;
            }
            const uint32_t off = (uint32_t)row * (KP * 2) + half * 64 + c * 16;
            *(uint4*)(sm + SMA + off) = make_uint4(hw[0], hw[1], hw[2], hw[3]);
        }
    }

    const uint4* wt4 = (const uint4*)g_wt;     // 512 uint4 per plane
    const int i0 = t, i1 = t + 256;
    const uint32_t so0 = (uint32_t)(i0 >> 3) * (KP * 2) + (i0 & 7) * 16;
    const uint32_t so1 = (uint32_t)(i1 >> 3) * (KP * 2) + (i1 & 7) * 16;

    // ---- Stage B plane kbase into buffer 0 ----
    {
        const size_t b0 = (size_t)kbase * 512;
        uint4 a0 = wt4[b0 + i0], a1 = wt4[b0 + i1];
        *(uint4*)(sm + SMB(0) + so0) = a0;
        *(uint4*)(sm + SMB(0) + so1) = a1;
    }
    __syncthreads();   // A tile + B plane kbase visible

    // ---- Load A fragments once (register-resident, 32 regs) ----
    uint32_t Ah[2][4][4];
    #pragma unroll
    for (int mt = 0; mt < 2; mt++) {
        #pragma unroll
        for (int kt = 0; kt < 4; kt++) {
            const int r0 = wm * 32 + mt * 16 + g;
            const int cb = kt * 16 + l4 * 2;
            Ah[mt][kt][0] = *(const uint32_t*)(sm + SMA + ((size_t)r0 * KP + cb) * 2);
            Ah[mt][kt][1] = *(const uint32_t*)(sm + SMA + ((size_t)(r0 + 8) * KP + cb) * 2);
            Ah[mt][kt][2] = *(const uint32_t*)(sm + SMA + ((size_t)r0 * KP + cb + 8) * 2);
            Ah[mt][kt][3] = *(const uint32_t*)(sm + SMA + ((size_t)(r0 + 8) * KP + cb + 8) * 2);
        }
    }

    // ---- Plane loop over this CTA's KCHUNK planes ----
    for (int kk = 0; kk < KCHUNK; kk++) {
        const int k = kbase + kk;
        const int p = kk & 1;
        uint4 ph0, ph1;
        const bool pre = (kk + 1 < KCHUNK);
        if (pre) {                        // issue LDGs early; MMAs hide latency
            const size_t base = (size_t)(k + 1) * 512;
            ph0 = wt4[base + i0];  ph1 = wt4[base + i1];
        }

        float C[2][4][4];
        #pragma unroll
        for (int mt = 0; mt < 2; mt++)
            #pragma unroll
            for (int nt = 0; nt < 4; nt++)
                #pragma unroll
                for (int i = 0; i < 4; i++) C[mt][nt][i] = 0.f;

        #pragma unroll
        for (int kt = 0; kt < 4; kt++) {
            #pragma unroll
            for (int nt = 0; nt < 4; nt++) {
                const uint32_t boff =
                    ((uint32_t)(wn * 32 + nt * 8 + g) * KP + kt * 16 + l4 * 2) * 2;
                const uint32_t b0 = *(const uint32_t*)(sm + SMB(p) + boff);
                const uint32_t b1 = *(const uint32_t*)(sm + SMB(p) + boff + 16);
                #pragma unroll
                for (int mt = 0; mt < 2; mt++)
                    MMA_FP16(C[mt][nt], Ah[mt][kt], b0, b1);
            }
        }

        if (pre) {                        // STS into the idle buffer (no race)
            *(uint4*)(sm + SMB(p ^ 1) + so0) = ph0;
            *(uint4*)(sm + SMB(p ^ 1) + so1) = ph1;
        }

        // Store this k-plane as fp16
        #pragma unroll
        for (int mt = 0; mt < 2; mt++) {
            const int n1 = n0 + wm * 32 + mt * 16 + g;
            const int n2 = n1 + 8;
            #pragma unroll
            for (int nt = 0; nt < 4; nt++) {
                const int col = wn * 32 + nt * 8 + l4 * 2;
                if (n1 < NUM_NODES)
                    *(__half2*)(g_gh + ((size_t)n1 * HIDDEN + k) * WIDTH + col) =
                        __floats2half2_rn(C[mt][nt][0], C[mt][nt][1]);
                if (n2 < NUM_NODES)
                    *(__half2*)(g_gh + ((size_t)n2 * HIDDEN + k) * WIDTH + col) =
                        __floats2half2_rn(C[mt][nt][2], C[mt][nt][3]);
            }
        }

        if (pre) __syncthreads();         // buf p^1 ready; buf p free next plane
    }
}

// ---------------------------------------------------------------------------
// SPLIT-K k_msg: TWO warps per sorted edge i, each covering 64 k-planes.
// Even warp seeds acc with xb, odd with 0; both atomicAdd into out[r].
// ---------------------------------------------------------------------------
__global__ __launch_bounds__(256) void k_msg(float* __restrict__ out) {
    __shared__ float hs[8][64];
    const int wi   = threadIdx.x >> 5;
    const int lane = threadIdx.x & 31;
    const int i    = blockIdx.x * 4 + (wi >> 1);
    const int half = wi & 1;
    if (i >= NUM_EDGES) return;

    hs[wi][lane]      = g_h[(size_t)i * HIDDEN + half * 64 + lane];
    hs[wi][lane + 32] = g_h[(size_t)i * HIDDEN + half * 64 + lane + 32];
    __syncwarp();

    const int s = g_ssnd[i];
    const int r = g_srcv[i];

    const __half2* gp =
        (const __half2*)(g_gh + ((size_t)s * HIDDEN + half * 64) * WIDTH) + lane;
    float2 acc = (half == 0)
        ? ((const float2*)(g_xb + (size_t)s * WIDTH))[lane]
        : make_float2(0.f, 0.f);

    #pragma unroll 8
    for (int k = 0; k < 64; k++) {
        float hk = hs[wi][k];
        if (hk != 0.f) {
            float2 gv = __half22float2(gp[k * 32]);   // 128B coalesced row
            acc.x = fmaf(hk, gv.x, acc.x);
            acc.y = fmaf(hk, gv.y, acc.y);
        }
    }

    atomicAdd(out + (size_t)r * WIDTH + 2 * lane,     acc.x);
    atomicAdd(out + (size_t)r * WIDTH + 2 * lane + 1, acc.y);
}

// ---------------------------------------------------------------------------
// Launch: fork-join two streams; gmat stays the 4th kernel submission so ncu
// keeps profiling it.
// ---------------------------------------------------------------------------
extern "C" void kernel_launch(void* const* d_in, const int* in_sizes, int n_in,
                              void* d_out, int out_size) {
    const float* x   = (const float*)d_in[0];
    const float* ea  = (const float*)d_in[1];
    const float* W1  = (const float*)d_in[2];
    const float* b1  = (const float*)d_in[3];
    const float* W2  = (const float*)d_in[4];
    const float* b2  = (const float*)d_in[5];
    const int*   snd = (const int*)d_in[6];
    const int*   rcv = (const int*)d_in[7];
    float* out = (float*)d_out;

    static cudaStream_t s2 = nullptr;
    static cudaEvent_t  evF = nullptr, evJ = nullptr;
    if (!s2) {
        cudaStreamCreateWithFlags(&s2, cudaStreamNonBlocking);
        cudaEventCreateWithFlags(&evF, cudaEventDisableTiming);
        cudaEventCreateWithFlags(&evJ, cudaEventDisableTiming);
        cudaFuncSetAttribute(k_gmat_hmma,
                             cudaFuncAttributeMaxDynamicSharedMemorySize, SM_TOT);
    }

    // ---- fork ----
    cudaEventRecord(evF, 0);
    cudaStreamWaitEvent(s2, evF, 0);

    // launches 1-2 (default stream)
    k_zero_cnt<<<(NUM_NODES + 255) / 256, 256>>>();
    k_count<<<(NUM_EDGES + 255) / 256, 256>>>(snd);

    // launches 3-4 (side stream; gmat is the 4th kernel submission -> profiled)
    k_prep_w2<<<(HIDDEN * WIDTH * WIDTH + 255) / 256, 256, 0, s2>>>(W2);
    {
        dim3 gg((NUM_NODES + 127) / 128, KSPLIT);   // (157, 2) = 314 CTAs
        k_gmat_hmma<<<gg, 256, SM_TOT, s2>>>(x);
    }
    cudaEventRecord(evJ, s2);

    // rest of default stream (independent of g)
    k_scan<<<1, 1024>>>();
    k_fill<<<(NUM_EDGES + 255) / 256, 256>>>(snd, rcv);
    k_hidden<<<(NUM_EDGES * HIDDEN + 255) / 256, 256>>>(ea, W1, b1);
    k_xb<<<(NUM_NODES + 15) / 16, 256>>>(x, b2);
    k_zero<<<(NUM_NODES * WIDTH + 255) / 256, 256>>>(out, NUM_NODES * WIDTH);

    // ---- join, then the gather/scatter ----
    cudaStreamWaitEvent((cudaStream_t)0, evJ, 0);
    k_msg<<<NUM_EDGES / 4, 256>>>(out);
}

// round 17
// speedup vs baseline: 1.2460x; 1.0811x over previous
#include <cuda_runtime.h>
#include <cuda_fp16.h>
#include <cstdint>

// Problem constants (fixed by the dataset)
#define NUM_NODES 20000
#define NUM_EDGES 65536
#define WIDTH     64
#define EDGE_FEAT 6
#define HIDDEN    128

// Scratch (allocation-free rule: __device__ globals)
__device__ float  g_h [(size_t)NUM_EDGES * HIDDEN];                // 33.5 MB (SORTED edge order)
__device__ __half g_gh[(size_t)NUM_NODES * HIDDEN * WIDTH];        // 328 MB  g[n][k][v] fp16
__device__ float  g_xb[(size_t)NUM_NODES * WIDTH];                 // 5.1 MB
__device__ __half g_wt[(size_t)HIDDEN * WIDTH * WIDTH];            // 2 MB  Wt[k][v][w] fp16
// edge sort-by-sender
__device__ int g_cnt [NUM_NODES];
__device__ int g_off [NUM_NODES + 1];
__device__ int g_inv [NUM_EDGES];     // original edge e -> sorted position
__device__ int g_ssnd[NUM_EDGES];     // sorted senders
__device__ int g_srcv[NUM_EDGES];     // sorted receivers

// Warp-level fp16 MMA (sm_80 PTX feature set — valid for plain sm_103 target)
#define MMA_FP16(c, a, b0, b1) \
    asm volatile("mma.sync.aligned.m16n8k16.row.col.f32.f16.f16.f32 " \
        "{%0,%1,%2,%3}, {%4,%5,%6,%7}, {%8,%9}, {%0,%1,%2,%3};" \
        : "+f"((c)[0]), "+f"((c)[1]), "+f"((c)[2]), "+f"((c)[3]) \
        : "r"((a)[0]), "r"((a)[1]), "r"((a)[2]), "r"((a)[3]), "r"(b0), "r"(b1))

// ---------------------------------------------------------------------------
// Zero kernels
// ---------------------------------------------------------------------------
__global__ void k_zero(float* __restrict__ out, int n) {
    int i = blockIdx.x * blockDim.x + threadIdx.x;
    if (i < n) out[i] = 0.f;
}
__global__ void k_zero_cnt() {
    int i = blockIdx.x * blockDim.x + threadIdx.x;
    if (i < NUM_NODES) g_cnt[i] = 0;
}

// ---------------------------------------------------------------------------
// Edge sort-by-sender: count -> scan (1 block) -> fill (inv/sorted arrays)
// ---------------------------------------------------------------------------
__global__ void k_count(const int* __restrict__ snd) {
    int i = blockIdx.x * blockDim.x + threadIdx.x;
    if (i < NUM_EDGES) atomicAdd(&g_cnt[snd[i]], 1);
}
__global__ __launch_bounds__(1024) void k_scan() {
    __shared__ int ps[1024];
    const int tid = threadIdx.x;
    const int CH  = (NUM_NODES + 1023) / 1024;   // 20
    const int base = tid * CH;
    int s = 0;
    #pragma unroll
    for (int j = 0; j < CH; j++) {
        int i = base + j;
        if (i < NUM_NODES) s += g_cnt[i];
    }
    ps[tid] = s;
    __syncthreads();
    for (int d = 1; d < 1024; d <<= 1) {         // Hillis-Steele inclusive scan
        int v = (tid >= d) ? ps[tid - d] : 0;
        __syncthreads();
        ps[tid] += v;
        __syncthreads();
    }
    int run = ps[tid] - s;                        // exclusive prefix of chunk
    #pragma unroll
    for (int j = 0; j < CH; j++) {
        int i = base + j;
        if (i < NUM_NODES) { g_off[i] = run; run += g_cnt[i]; g_cnt[i] = 0; }
    }
    if (tid == 1023) g_off[NUM_NODES] = run;
}
__global__ void k_fill(const int* __restrict__ snd, const int* __restrict__ rcv) {
    int i = blockIdx.x * blockDim.x + threadIdx.x;
    if (i >= NUM_EDGES) return;
    int s = snd[i];
    int pos = g_off[s] + atomicAdd(&g_cnt[s], 1);
    g_inv[i]     = pos;
    g_ssnd[pos]  = s;
    g_srcv[pos]  = rcv[i];
}

// ---------------------------------------------------------------------------
// h[pos][k] = relu( sum_f edge_attr[e][f]*W1[f][k] + b1[k] ), pos = g_inv[e]
// ---------------------------------------------------------------------------
__global__ void k_hidden(const float* __restrict__ ea,
                         const float* __restrict__ W1,
                         const float* __restrict__ b1) {
    int idx = blockIdx.x * blockDim.x + threadIdx.x;
    if (idx >= NUM_EDGES * HIDDEN) return;
    int e = idx >> 7;
    int j = idx & (HIDDEN - 1);
    const float* a = ea + (size_t)e * EDGE_FEAT;
    float s = __ldg(b1 + j);
    #pragma unroll
    for (int f = 0; f < EDGE_FEAT; f++)
        s = fmaf(__ldg(a + f), __ldg(W1 + f * HIDDEN + j), s);
    g_h[(size_t)g_inv[e] * HIDDEN + j] = fmaxf(s, 0.f);
}

// ---------------------------------------------------------------------------
// Wt[k][v][w] = W2[k][w*64+v] as fp16 (col-major B for mma.row.col)
// ---------------------------------------------------------------------------
__global__ void k_prep_w2(const float* __restrict__ W2) {
    int idx = blockIdx.x * blockDim.x + threadIdx.x;
    if (idx >= HIDDEN * WIDTH * WIDTH) return;
    int k = idx >> 12, rem = idx & 4095, v = rem >> 6, w = rem & 63;
    g_wt[idx] = __float2half_rn(W2[(size_t)k * 4096 + w * 64 + v]);
}

// ---------------------------------------------------------------------------
// xb[n][v] = sum_w x[n][w]*b2[w*64+v].  16 nodes/block, 4 outputs/thread.
// ---------------------------------------------------------------------------
__global__ __launch_bounds__(256) void k_xb(const float* __restrict__ x,
                                            const float* __restrict__ b2) {
    __shared__ float b2s[WIDTH * WIDTH];       // 16 KB, [w][v]
    __shared__ float xs[16][WIDTH + 1];        // 16 node rows, padded
    const int t = threadIdx.x;
    for (int i = t; i < WIDTH * WIDTH; i += 256)
        b2s[i] = b2[i];
    {
        const int n0 = blockIdx.x * 16;
        for (int i = t; i < 16 * WIDTH; i += 256) {
            int nl = i >> 6, w = i & 63;
            int n = n0 + nl;
            xs[nl][w] = (n < NUM_NODES) ? x[(size_t)n * WIDTH + w] : 0.f;
        }
    }
    __syncthreads();

    const int nl = t >> 4;
    const int v4 = t & 15;
    float4 acc = make_float4(0.f, 0.f, 0.f, 0.f);
    #pragma unroll 8
    for (int w = 0; w < WIDTH; w++) {
        const float xv = xs[nl][w];
        const float4 b = *(const float4*)&b2s[w * WIDTH + v4 * 4];
        acc.x = fmaf(xv, b.x, acc.x);
        acc.y = fmaf(xv, b.y, acc.y);
        acc.z = fmaf(xv, b.z, acc.z);
        acc.w = fmaf(xv, b.w, acc.w);
    }
    const int n = blockIdx.x * 16 + nl;
    if (n < NUM_NODES)
        *(float4*)(g_xb + (size_t)n * WIDTH + v4 * 4) = acc;
}

// ---------------------------------------------------------------------------
// HMMA g-GEMM: g[n][k][v] = sum_w x[n][w]*Wt[k][v][w], fp16 in/fp32 acc/fp16 out.
// GRID (157, 4): CTA = 128-node M-tile x 32-plane slice (tail 18% vs 41%).
// R16 profile: L1 58.8% >> tensor 19.8% -> epilogue STG.32 scatter (8 lines/
// instr + half-filled 32B sectors) was the bottleneck. NEW: C tile staged to
// swizzled smem as fp16, then 4x coalesced STG.128/thread (8x fewer store
// wavefronts, full sectors). Double-buffered stage, ONE barrier/plane kept.
// ---------------------------------------------------------------------------
#define KP 72
#define SMA 0                                  // 128 rows * 144B = 18432
#define SMB_BASE (128 * KP * 2)                // 18432
#define SMB(p) (SMB_BASE + (p) * 9216)         // B: 64 rows * 144B each
#define SMS_BASE (SMB_BASE + 2 * 9216)         // 36864
#define SMS(p) (SMS_BASE + (p) * 16384)        // stage: 128 rows * 128B fp16
#define SM_TOT (SMS_BASE + 2 * 16384)          // 69632 B (x2 CTAs = 139KB)
#define KSPLIT 4
#define KCHUNK (HIDDEN / KSPLIT)               // 32 planes per CTA

__global__ __launch_bounds__(256, 2) void k_gmat_hmma(const float* __restrict__ x) {
    extern __shared__ char sm[];
    const int t     = threadIdx.x;
    const int lane  = t & 31;
    const int warp  = t >> 5;
    const int wm    = warp & 3;
    const int wn    = warp >> 2;
    const int n0    = blockIdx.x * 128;
    const int kbase = blockIdx.y * KCHUNK;
    const int g     = lane >> 2;
    const int l4    = lane & 3;

    // ---- Stage A tile: x rows -> fp16, padded KP-stride rows ----
    {
        const int row  = t >> 1;
        const int half = t & 1;
        const int n    = n0 + row;
        float4 f4[8];
        if (n < NUM_NODES) {
            const float4* xr = (const float4*)(x + (size_t)n * WIDTH) + half * 8;
            #pragma unroll
            for (int j = 0; j < 8; j++) f4[j] = xr[j];
        } else {
            #pragma unroll
            for (int j = 0; j < 8; j++) f4[j] = make_float4(0.f, 0.f, 0.f, 0.f);
        }
        const float* f = (const float*)f4;
        #pragma unroll
        for (int c = 0; c < 4; c++) {
            uint32_t hw[4];
            #pragma unroll
            for (int j = 0; j < 4; j++) {
                __half2 h2 = __floats2half2_rn(f[c * 8 + j * 2], f[c * 8 + j * 2 + 1]);
                hw[j] = *(uint32_t*)&h2;
            }
            const uint32_t off = (uint32_t)row * (KP * 2) + half * 64 + c * 16;
            *(uint4*)(sm + SMA + off) = make_uint4(hw[0], hw[1], hw[2], hw[3]);
        }
    }

    const uint4* wt4 = (const uint4*)g_wt;     // 512 uint4 per plane
    const int i0 = t, i1 = t + 256;
    const uint32_t so0 = (uint32_t)(i0 >> 3) * (KP * 2) + (i0 & 7) * 16;
    const uint32_t so1 = (uint32_t)(i1 >> 3) * (KP * 2) + (i1 & 7) * 16;

    // ---- Stage B plane kbase into buffer 0 ----
    {
        const size_t b0 = (size_t)kbase * 512;
        uint4 a0 = wt4[b0 + i0], a1 = wt4[b0 + i1];
        *(uint4*)(sm + SMB(0) + so0) = a0;
        *(uint4*)(sm + SMB(0) + so1) = a1;
    }
    __syncthreads();   // A tile + B plane kbase visible

    // ---- Load A fragments once (register-resident, 32 regs) ----
    uint32_t Ah[2][4][4];
    #pragma unroll
    for (int mt = 0; mt < 2; mt++) {
        #pragma unroll
        for (int kt = 0; kt < 4; kt++) {
            const int r0 = wm * 32 + mt * 16 + g;
            const int cb = kt * 16 + l4 * 2;
            Ah[mt][kt][0] = *(const uint32_t*)(sm + SMA + ((size_t)r0 * KP + cb) * 2);
            Ah[mt][kt][1] = *(const uint32_t*)(sm + SMA + ((size_t)(r0 + 8) * KP + cb) * 2);
            Ah[mt][kt][2] = *(const uint32_t*)(sm + SMA + ((size_t)r0 * KP + cb + 8) * 2);
            Ah[mt][kt][3] = *(const uint32_t*)(sm + SMA + ((size_t)(r0 + 8) * KP + cb + 8) * 2);
        }
    }

    // ---- Plane loop over this CTA's KCHUNK planes ----
    for (int kk = 0; kk < KCHUNK; kk++) {
        const int k = kbase + kk;
        const int p = kk & 1;
        uint4 ph0, ph1;
        const bool pre = (kk + 1 < KCHUNK);
        if (pre) {                        // issue LDGs early; MMAs hide latency
            const size_t base = (size_t)(k + 1) * 512;
            ph0 = wt4[base + i0];  ph1 = wt4[base + i1];
        }

        float C[2][4][4];
        #pragma unroll
        for (int mt = 0; mt < 2; mt++)
            #pragma unroll
            for (int nt = 0; nt < 4; nt++)
                #pragma unroll
                for (int i = 0; i < 4; i++) C[mt][nt][i] = 0.f;

        #pragma unroll
        for (int kt = 0; kt < 4; kt++) {
            #pragma unroll
            for (int nt = 0; nt < 4; nt++) {
                const uint32_t boff =
                    ((uint32_t)(wn * 32 + nt * 8 + g) * KP + kt * 16 + l4 * 2) * 2;
                const uint32_t b0 = *(const uint32_t*)(sm + SMB(p) + boff);
                const uint32_t b1 = *(const uint32_t*)(sm + SMB(p) + boff + 16);
                #pragma unroll
                for (int mt = 0; mt < 2; mt++)
                    MMA_FP16(C[mt][nt], Ah[mt][kt], b0, b1);
            }
        }

        if (pre) {                        // STS B into the idle buffer (no race)
            *(uint4*)(sm + SMB(p ^ 1) + so0) = ph0;
            *(uint4*)(sm + SMB(p ^ 1) + so1) = ph1;
        }

        // ---- STS C tile -> swizzled fp16 stage p (conflict-free: l4 bits
        //      2-3, g bits 4-6 disjoint under XOR (row&7)<<4) ----
        #pragma unroll
        for (int mt = 0; mt < 2; mt++) {
            const int r1 = wm * 32 + mt * 16 + g;       // r1&7 == g
            #pragma unroll
            for (int nt = 0; nt < 4; nt++) {
                const int colb = (wn * 32 + nt * 8 + l4 * 2) * 2;   // byte in row
                const uint32_t sw = (uint32_t)colb ^ ((uint32_t)g << 4);
                *(__half2*)(sm + SMS(p) + r1 * 128 + sw) =
                    __floats2half2_rn(C[mt][nt][0], C[mt][nt][1]);
                *(__half2*)(sm + SMS(p) + (r1 + 8) * 128 + sw) =
                    __floats2half2_rn(C[mt][nt][2], C[mt][nt][3]);
            }
        }

        __syncthreads();   // publishes stage p + B p^1; stage p^1 drained (kk-1)

        // ---- Coalesced STG.128: 4 x uint4 per thread, full 128B rows ----
        #pragma unroll
        for (int q = 0; q < 4; q++) {
            const int i   = q * 256 + t;               // 0..1023
            const int row = i >> 3;
            const int cb  = (i & 7) * 16;              // logical byte chunk
            const uint32_t swb = (uint32_t)cb ^ (((uint32_t)row & 7) << 4);
            const uint4 val = *(const uint4*)(sm + SMS(p) + row * 128 + swb);
            const int n = n0 + row;
            if (n < NUM_NODES)
                ((uint4*)(g_gh + ((size_t)n * HIDDEN + k) * WIDTH))[i & 7] = val;
        }
    }
}

// ---------------------------------------------------------------------------
// SPLIT-K k_msg: TWO warps per sorted edge i, each covering 64 k-planes.
// Even warp seeds acc with xb, odd with 0; both atomicAdd into out[r].
// ---------------------------------------------------------------------------
__global__ __launch_bounds__(256) void k_msg(float* __restrict__ out) {
    __shared__ float hs[8][64];
    const int wi   = threadIdx.x >> 5;
    const int lane = threadIdx.x & 31;
    const int i    = blockIdx.x * 4 + (wi >> 1);
    const int half = wi & 1;
    if (i >= NUM_EDGES) return;

    hs[wi][lane]      = g_h[(size_t)i * HIDDEN + half * 64 + lane];
    hs[wi][lane + 32] = g_h[(size_t)i * HIDDEN + half * 64 + lane + 32];
    __syncwarp();

    const int s = g_ssnd[i];
    const int r = g_srcv[i];

    const __half2* gp =
        (const __half2*)(g_gh + ((size_t)s * HIDDEN + half * 64) * WIDTH) + lane;
    float2 acc = (half == 0)
        ? ((const float2*)(g_xb + (size_t)s * WIDTH))[lane]
        : make_float2(0.f, 0.f);

    #pragma unroll 8
    for (int k = 0; k < 64; k++) {
        float hk = hs[wi][k];
        if (hk != 0.f) {
            float2 gv = __half22float2(gp[k * 32]);   // 128B coalesced row
            acc.x = fmaf(hk, gv.x, acc.x);
            acc.y = fmaf(hk, gv.y, acc.y);
        }
    }

    atomicAdd(out + (size_t)r * WIDTH + 2 * lane,     acc.x);
    atomicAdd(out + (size_t)r * WIDTH + 2 * lane + 1, acc.y);
}

// ---------------------------------------------------------------------------
// Launch: fork-join two streams; gmat stays the 4th kernel submission so ncu
// keeps profiling it.
// ---------------------------------------------------------------------------
extern "C" void kernel_launch(void* const* d_in, const int* in_sizes, int n_in,
                              void* d_out, int out_size) {
    const float* x   = (const float*)d_in[0];
    const float* ea  = (const float*)d_in[1];
    const float* W1  = (const float*)d_in[2];
    const float* b1  = (const float*)d_in[3];
    const float* W2  = (const float*)d_in[4];
    const float* b2  = (const float*)d_in[5];
    const int*   snd = (const int*)d_in[6];
    const int*   rcv = (const int*)d_in[7];
    float* out = (float*)d_out;

    static cudaStream_t s2 = nullptr;
    static cudaEvent_t  evF = nullptr, evJ = nullptr;
    if (!s2) {
        cudaStreamCreateWithFlags(&s2, cudaStreamNonBlocking);
        cudaEventCreateWithFlags(&evF, cudaEventDisableTiming);
        cudaEventCreateWithFlags(&evJ, cudaEventDisableTiming);
        cudaFuncSetAttribute(k_gmat_hmma,
                             cudaFuncAttributeMaxDynamicSharedMemorySize, SM_TOT);
    }

    // ---- fork ----
    cudaEventRecord(evF, 0);
    cudaStreamWaitEvent(s2, evF, 0);

    // launches 1-2 (default stream)
    k_zero_cnt<<<(NUM_NODES + 255) / 256, 256>>>();
    k_count<<<(NUM_EDGES + 255) / 256, 256>>>(snd);

    // launches 3-4 (side stream; gmat is the 4th kernel submission -> profiled)
    k_prep_w2<<<(HIDDEN * WIDTH * WIDTH + 255) / 256, 256, 0, s2>>>(W2);
    {
        dim3 gg((NUM_NODES + 127) / 128, KSPLIT);   // (157, 4) = 628 CTAs
        k_gmat_hmma<<<gg, 256, SM_TOT, s2>>>(x);
    }
    cudaEventRecord(evJ, s2);

    // rest of default stream (independent of g)
    k_scan<<<1, 1024>>>();
    k_fill<<<(NUM_EDGES + 255) / 256, 256>>>(snd, rcv);
    k_hidden<<<(NUM_EDGES * HIDDEN + 255) / 256, 256>>>(ea, W1, b1);
    k_xb<<<(NUM_NODES + 15) / 16, 256>>>(x, b2);
    k_zero<<<(NUM_NODES * WIDTH + 255) / 256, 256>>>(out, NUM_NODES * WIDTH);

    // ---- join, then the gather/scatter ----
    cudaStreamWaitEvent((cudaStream_t)0, evJ, 0);
    k_msg<<<NUM_EDGES / 4, 256>>>(out);
}